// round 13
// baseline (speedup 1.0000x reference)
#include <cuda_runtime.h>
#include <cuda_fp16.h>
#include <math.h>
#include <stdint.h>

#define NNODES 50000
#define EEDGES 800000
#define ETOT   (EEDGES + NNODES)
#define DHID   128
#define DFEAT  256          // HEADS * HID
#define NEG_SLOPE 0.2f
#define EPSV 1e-16f

// ---------------- scratch (no allocation allowed; zero-initialized at load) ----------------
__device__ __half g_h1[NNODES * DFEAT];
__device__ float  g_agg1[NNODES * DFEAT];
__device__ __half g_h2[NNODES * DFEAT];
__device__ float  g_agg2[NNODES * DFEAT];
__device__ float  g_as[NNODES * 2];
__device__ float  g_ad[NNODES * 2];
__device__ float  g_wc[DFEAT + 1];
__device__ uint32_t g_w1hi[DFEAT * DHID / 2];   // W1 split, packed k-pairs [N][K/2]
__device__ uint32_t g_w1lo[DFEAT * DHID / 2];
__device__ uint32_t g_w2hi[DFEAT * DFEAT / 2];  // W2 split
__device__ uint32_t g_w2lo[DFEAT * DFEAT / 2];
__device__ int    g_cnt[NNODES];      // self-cleaning (scan_final re-zeroes)
__device__ int    g_rowptr[NNODES];
__device__ int    g_cursor[NNODES];   // after scatter: row end
__device__ int    g_colidx[ETOT];
__device__ int    g_bsum[256];

// ================= weight pre-split: W[k][n] fp32 -> hi/lo fp16 k-pairs [n][k/2] =================
__global__ void wsplit_kernel(const float* __restrict__ W,
                              uint32_t* __restrict__ hi, uint32_t* __restrict__ lo,
                              int K, int N) {
    int t = blockIdx.x * 256 + threadIdx.x;
    int total = N * (K >> 1);
    if (t >= total) return;
    int n = t / (K >> 1), k2 = t % (K >> 1);
    float x = W[(size_t)(2 * k2) * N + n];
    float y = W[(size_t)(2 * k2 + 1) * N + n];
    __half2 h = __floats2half2_rn(x, y);
    float2 hf = __half22float2(h);
    __half2 l = __floats2half2_rn(x - hf.x, y - hf.y);
    hi[t] = *(uint32_t*)&h;
    lo[t] = *(uint32_t*)&l;
}

// ================= CSR construction =================
__global__ void count_kernel(const int* __restrict__ ei, int* __restrict__ cnt,
                             int E, int Etot) {
    int t = blockIdx.x * blockDim.x + threadIdx.x;
    if (t >= Etot) return;
    int d = (t < E) ? ei[E + t] : (t - E);
    atomicAdd(&cnt[d], 1);
}

__global__ void scan_block_sums(const int* __restrict__ cnt, int* __restrict__ bsum, int N) {
    __shared__ int sh[256];
    int tid = threadIdx.x;
    int i = blockIdx.x * 256 + tid;
    sh[tid] = (i < N) ? cnt[i] : 0;
    __syncthreads();
    for (int s = 128; s > 0; s >>= 1) {
        if (tid < s) sh[tid] += sh[tid + s];
        __syncthreads();
    }
    if (tid == 0) bsum[blockIdx.x] = sh[0];
}

__global__ void scan_bsums(int* bsum, int nb) {
    __shared__ int sh[256];
    int tid = threadIdx.x;
    int v0 = (tid < nb) ? bsum[tid] : 0;
    sh[tid] = v0;
    __syncthreads();
    for (int off = 1; off < 256; off <<= 1) {
        int v = (tid >= off) ? sh[tid - off] : 0;
        __syncthreads();
        sh[tid] += v;
        __syncthreads();
    }
    if (tid < nb) bsum[tid] = sh[tid] - v0;   // exclusive
}

__global__ void scan_final(int* __restrict__ cnt, const int* __restrict__ bsum,
                           int* __restrict__ rowptr, int* __restrict__ cursor, int N) {
    __shared__ int sh[256];
    int tid = threadIdx.x;
    int i = blockIdx.x * 256 + tid;
    int v0 = (i < N) ? cnt[i] : 0;
    sh[tid] = v0;
    __syncthreads();
    for (int off = 1; off < 256; off <<= 1) {
        int v = (tid >= off) ? sh[tid - off] : 0;
        __syncthreads();
        sh[tid] += v;
        __syncthreads();
    }
    if (i < N) {
        int excl = sh[tid] - v0 + bsum[blockIdx.x];
        rowptr[i] = excl;
        cursor[i] = excl;
        cnt[i] = 0;   // self-clean for next graph replay
    }
}

__global__ void scatter_kernel(const int* __restrict__ ei, int* __restrict__ cursor,
                               int* __restrict__ colidx, int E, int Etot) {
    int t = blockIdx.x * blockDim.x + threadIdx.x;
    if (t >= Etot) return;
    int s, d;
    if (t < E) { s = ei[t]; d = ei[E + t]; } else { s = d = t - E; }
    int pos = atomicAdd(&cursor[d], 1);
    colidx[pos] = s;
}

// ================= double-fp16 tensor-core GEMM (4 CTAs/SM forced) =================
__device__ __forceinline__ void mma_f16(float* c, const uint32_t* a, const uint32_t* b) {
    asm volatile(
        "mma.sync.aligned.m16n8k16.row.col.f32.f16.f16.f32 "
        "{%0,%1,%2,%3}, {%4,%5,%6,%7}, {%8,%9}, {%0,%1,%2,%3};"
        : "+f"(c[0]), "+f"(c[1]), "+f"(c[2]), "+f"(c[3])
        : "r"(a[0]), "r"(a[1]), "r"(a[2]), "r"(a[3]), "r"(b[0]), "r"(b[1]));
}

template <int FUSE_RELU>
__global__ void __launch_bounds__(256, 4) gemm_f16_kernel(
    const float* __restrict__ A,
    const uint32_t* __restrict__ Whi, const uint32_t* __restrict__ Wlo,
    const float* __restrict__ bias, __half* __restrict__ C,
    int M, int N, int K)
{
    __shared__ uint32_t Ah[128][12];   // [row][k2], pad 12: frag bank 12*gid+tig bijective
    __shared__ uint32_t Al[128][12];
    __shared__ uint32_t Bh[64][12];    // [n][k2]
    __shared__ uint32_t Bl[64][12];

    const int tid  = threadIdx.x;
    const int lane = tid & 31;
    const int warp = tid >> 5;
    const int wm   = warp & 3;     // m warp: wm*32
    const int wn   = warp >> 2;    // n warp: wn*32
    const int gid  = lane >> 2;
    const int tig  = lane & 3;
    const int m0 = blockIdx.x * 128;
    const int n0 = blockIdx.y * 64;
    const int K2 = K >> 1;

    float c_[2][4][4];
#pragma unroll
    for (int fm = 0; fm < 2; fm++)
#pragma unroll
        for (int fn = 0; fn < 4; fn++)
#pragma unroll
            for (int j = 0; j < 4; j++) c_[fm][fn][j] = 0.f;

    for (int k0 = 0; k0 < K; k0 += 16) {
        // ---- A tile (128 x 16): 512 float4, 2 per thread; split to hi/lo k-pairs ----
#pragma unroll
        for (int it = 0; it < 2; it++) {
            int idx = tid + it * 256;
            int row = idx >> 2, c4 = idx & 3;
            int gm = m0 + row;
            float4 f = make_float4(0.f, 0.f, 0.f, 0.f);
            if (gm < M) f = *(const float4*)&A[(size_t)gm * K + k0 + c4 * 4];
            if (FUSE_RELU) {
                float4 bb = *(const float4*)&bias[k0 + c4 * 4];
                f.x = fmaxf(f.x + bb.x, 0.f);
                f.y = fmaxf(f.y + bb.y, 0.f);
                f.z = fmaxf(f.z + bb.z, 0.f);
                f.w = fmaxf(f.w + bb.w, 0.f);
            }
            __half2 h01 = __floats2half2_rn(f.x, f.y);
            __half2 h23 = __floats2half2_rn(f.z, f.w);
            float2 hf01 = __half22float2(h01);
            float2 hf23 = __half22float2(h23);
            __half2 l01 = __floats2half2_rn(f.x - hf01.x, f.y - hf01.y);
            __half2 l23 = __floats2half2_rn(f.z - hf23.x, f.w - hf23.y);
            *(uint2*)&Ah[row][c4 * 2] = make_uint2(*(uint32_t*)&h01, *(uint32_t*)&h23);
            *(uint2*)&Al[row][c4 * 2] = make_uint2(*(uint32_t*)&l01, *(uint32_t*)&l23);
        }
        // ---- B tile (64 n x 8 k2): 256 uint2, 1 per thread (pre-split weights) ----
        {
            int n = tid >> 2;             // 0..63
            int kq = (tid & 3) * 2;       // 0,2,4,6
            size_t gidx = (size_t)(n0 + n) * K2 + (k0 >> 1) + kq;
            uint2 hv = *(const uint2*)&Whi[gidx];
            uint2 lv = *(const uint2*)&Wlo[gidx];
            *(uint2*)&Bh[n][kq] = hv;
            *(uint2*)&Bl[n][kq] = lv;
        }
        __syncthreads();

        uint32_t ah[2][4], al[2][4], bh[4][2], bl[4][2];
#pragma unroll
        for (int fm = 0; fm < 2; fm++) {
            int r = wm * 32 + fm * 16;
            ah[fm][0] = Ah[r + gid][tig];       al[fm][0] = Al[r + gid][tig];
            ah[fm][1] = Ah[r + gid + 8][tig];   al[fm][1] = Al[r + gid + 8][tig];
            ah[fm][2] = Ah[r + gid][tig + 4];   al[fm][2] = Al[r + gid][tig + 4];
            ah[fm][3] = Ah[r + gid + 8][tig + 4]; al[fm][3] = Al[r + gid + 8][tig + 4];
        }
#pragma unroll
        for (int fn = 0; fn < 4; fn++) {
            int cc = wn * 32 + fn * 8 + gid;
            bh[fn][0] = Bh[cc][tig];     bl[fn][0] = Bl[cc][tig];
            bh[fn][1] = Bh[cc][tig + 4]; bl[fn][1] = Bl[cc][tig + 4];
        }
#pragma unroll
        for (int fm = 0; fm < 2; fm++)
#pragma unroll
            for (int fn = 0; fn < 4; fn++) {
                mma_f16(c_[fm][fn], ah[fm], bh[fn]);   // hi*hi
                mma_f16(c_[fm][fn], ah[fm], bl[fn]);   // hi*lo
                mma_f16(c_[fm][fn], al[fm], bh[fn]);   // lo*hi
            }
        __syncthreads();
    }

    // ---- epilogue: fp16 stores ----
#pragma unroll
    for (int fm = 0; fm < 2; fm++)
#pragma unroll
        for (int fn = 0; fn < 4; fn++) {
            int gm = m0 + wm * 32 + fm * 16 + gid;
            int gn = n0 + wn * 32 + fn * 8 + 2 * tig;
            if (gm < M)
                *(__half2*)&C[(size_t)gm * N + gn] =
                    __floats2half2_rn(c_[fm][fn][0], c_[fm][fn][1]);
            if (gm + 8 < M)
                *(__half2*)&C[(size_t)(gm + 8) * N + gn] =
                    __floats2half2_rn(c_[fm][fn][2], c_[fm][fn][3]);
        }
}

// ================= attention logits (fp16 h) =================
__global__ void alpha_kernel(const __half* __restrict__ h,
                             const float* __restrict__ a_src,
                             const float* __restrict__ a_dst,
                             float* __restrict__ as_out, float* __restrict__ ad_out,
                             int N)
{
    int gw = (blockIdx.x * blockDim.x + threadIdx.x) >> 5;
    int lane = threadIdx.x & 31;
    if (gw >= N * 2) return;
    int n = gw >> 1, hh = gw & 1;
    const __half2* hp = (const __half2*)(h + (size_t)n * DFEAT + hh * DHID);
    __half2 p0 = hp[lane * 2], p1 = hp[lane * 2 + 1];
    float2 f0 = __half22float2(p0), f1 = __half22float2(p1);
    float4 s = *(const float4*)&a_src[hh * DHID + lane * 4];
    float4 d = *(const float4*)&a_dst[hh * DHID + lane * 4];
    float accs = f0.x * s.x + f0.y * s.y + f1.x * s.z + f1.y * s.w;
    float accd = f0.x * d.x + f0.y * d.y + f1.x * d.z + f1.y * d.w;
#pragma unroll
    for (int o = 16; o; o >>= 1) {
        accs += __shfl_xor_sync(0xffffffffu, accs, o);
        accd += __shfl_xor_sync(0xffffffffu, accd, o);
    }
    if (lane == 0) { as_out[gw] = accs; ad_out[gw] = accd; }
}

// ================= fused CSR softmax-aggregation =================
// Warp-batched: per 32-edge chunk, lane l loads colidx[base+l] and gathers
// as_in[s_l] once (coalesced); per-edge values come from __shfl. Only the
// h-row gather stays per-edge, software-pipelined one deep.
__global__ void agg_csr_kernel(const int* __restrict__ rowptr, const int* __restrict__ rowend,
                               const int* __restrict__ colidx,
                               const __half* __restrict__ h,
                               const float* __restrict__ as_in, const float* __restrict__ ad_in,
                               float* __restrict__ out, int N)
{
    int gw = (blockIdx.x * blockDim.x + threadIdx.x) >> 5;
    int lane = threadIdx.x & 31;
    if (gw >= N) return;
    int start = rowptr[gw];
    int end   = rowend[gw];
    float2 adv = ((const float2*)ad_in)[gw];
    const uint4* h4 = (const uint4*)h;   // 8 fp16 per uint4; node stride = 32

    float acc[8];
#pragma unroll
    for (int j = 0; j < 8; j++) acc[j] = 0.f;
    float den0 = 0.f, den1 = 0.f;
    const bool head0 = lane < 16;

    for (int base = start; base < end; base += 32) {
        int m = end - base; if (m > 32) m = 32;
        int idx = base + lane;
        int sl = __ldg(&colidx[idx < end ? idx : start]);
        float2 avl = ((const float2*)as_in)[sl];   // one gather covers 32 edges

        int s0 = __shfl_sync(0xffffffffu, sl, 0);
        uint4 v = h4[(size_t)s0 * 32 + lane];      // prologue for this chunk
        for (int j = 0; j < m; j++) {
            uint4 vc = v;
            if (j + 1 < m) {
                int sn = __shfl_sync(0xffffffffu, sl, j + 1);
                v = h4[(size_t)sn * 32 + lane];
            }
            float avx = __shfl_sync(0xffffffffu, avl.x, j);
            float avy = __shfl_sync(0xffffffffu, avl.y, j);
            float e0 = avx + adv.x;  e0 = e0 > 0.f ? e0 : NEG_SLOPE * e0;
            float e1 = avy + adv.y;  e1 = e1 > 0.f ? e1 : NEG_SLOPE * e1;
            float w0 = __expf(e0);
            float w1 = __expf(e1);
            den0 += w0;  den1 += w1;
            float w = head0 ? w0 : w1;
            float2 a = __half22float2(*(const __half2*)&vc.x);
            float2 b = __half22float2(*(const __half2*)&vc.y);
            float2 c = __half22float2(*(const __half2*)&vc.z);
            float2 d = __half22float2(*(const __half2*)&vc.w);
            acc[0] = fmaf(w, a.x, acc[0]); acc[1] = fmaf(w, a.y, acc[1]);
            acc[2] = fmaf(w, b.x, acc[2]); acc[3] = fmaf(w, b.y, acc[3]);
            acc[4] = fmaf(w, c.x, acc[4]); acc[5] = fmaf(w, c.y, acc[5]);
            acc[6] = fmaf(w, d.x, acc[6]); acc[7] = fmaf(w, d.y, acc[7]);
        }
    }
    float r = 1.f / ((head0 ? den0 : den1) + EPSV);
    float* op = out + (size_t)gw * DFEAT + lane * 8;
    *(float4*)op       = make_float4(acc[0] * r, acc[1] * r, acc[2] * r, acc[3] * r);
    *(float4*)(op + 4) = make_float4(acc[4] * r, acc[5] * r, acc[6] * r, acc[7] * r);
}

// ================= collapsed post-MLP =================
__global__ void wc_kernel(const float* __restrict__ Wp1, const float* __restrict__ bp1,
                          const float* __restrict__ Wp2, const float* __restrict__ bp2,
                          float* __restrict__ wc)
{
    int i = threadIdx.x;  // 256 threads
    float acc = 0.f;
    for (int j = 0; j < DHID; j++) acc += Wp1[i * DHID + j] * Wp2[j];
    wc[i] = acc;
    if (i == 0) {
        float b = 0.f;
        for (int j = 0; j < DHID; j++) b += bp1[j] * Wp2[j];
        wc[DFEAT] = b + bp2[0];
    }
}

__global__ void final_kernel(const float* __restrict__ agg2,
                             const float* __restrict__ b2,
                             const float* __restrict__ wc,
                             float* __restrict__ out, int N)
{
    int gw = (blockIdx.x * blockDim.x + threadIdx.x) >> 5;
    int lane = threadIdx.x & 31;
    if (gw >= N) return;
    const float* hp = agg2 + (size_t)gw * DFEAT;
    float acc = 0.f;
#pragma unroll
    for (int r = 0; r < 2; r++) {
        int cidx = r * 128 + lane * 4;
        float4 v  = *(const float4*)&hp[cidx];
        float4 bb = *(const float4*)&b2[cidx];
        float4 ww = *(const float4*)&wc[cidx];
        acc += fmaxf(v.x + bb.x, 0.f) * ww.x;
        acc += fmaxf(v.y + bb.y, 0.f) * ww.y;
        acc += fmaxf(v.z + bb.z, 0.f) * ww.z;
        acc += fmaxf(v.w + bb.w, 0.f) * ww.w;
    }
#pragma unroll
    for (int o = 16; o; o >>= 1) acc += __shfl_xor_sync(0xffffffffu, acc, o);
    if (lane == 0) {
        float z = acc + wc[DFEAT];
        out[gw] = 1.f / (1.f + expf(-z));
    }
}

// ================= launch (fork-join: CSR/wsplit2/wc overlap gemm1 chain) =================
extern "C" void kernel_launch(void* const* d_in, const int* in_sizes, int n_in,
                              void* d_out, int out_size)
{
    const float* x      = (const float*)d_in[0];
    const int*   ei     = (const int*)  d_in[1];
    const float* W1     = (const float*)d_in[2];
    const float* a_src1 = (const float*)d_in[3];
    const float* a_dst1 = (const float*)d_in[4];
    const float* b1     = (const float*)d_in[5];
    const float* W2     = (const float*)d_in[6];
    const float* a_src2 = (const float*)d_in[7];
    const float* a_dst2 = (const float*)d_in[8];
    const float* b2     = (const float*)d_in[9];
    const float* Wp1    = (const float*)d_in[10];
    const float* bp1    = (const float*)d_in[11];
    const float* Wp2    = (const float*)d_in[12];
    const float* bp2    = (const float*)d_in[13];

    const int N = in_sizes[0] / 128;
    const int E = in_sizes[1] / 2;
    const int Etot = E + N;

    __half *h1, *h2;
    float *agg1, *agg2, *as, *ad, *wc;
    uint32_t *w1hi, *w1lo, *w2hi, *w2lo;
    int *cnt, *rowptr, *cursor, *colidx, *bsum;
    cudaGetSymbolAddress((void**)&h1,   g_h1);
    cudaGetSymbolAddress((void**)&agg1, g_agg1);
    cudaGetSymbolAddress((void**)&h2,   g_h2);
    cudaGetSymbolAddress((void**)&agg2, g_agg2);
    cudaGetSymbolAddress((void**)&as,   g_as);
    cudaGetSymbolAddress((void**)&ad,   g_ad);
    cudaGetSymbolAddress((void**)&wc,   g_wc);
    cudaGetSymbolAddress((void**)&w1hi, g_w1hi);
    cudaGetSymbolAddress((void**)&w1lo, g_w1lo);
    cudaGetSymbolAddress((void**)&w2hi, g_w2hi);
    cudaGetSymbolAddress((void**)&w2lo, g_w2lo);
    cudaGetSymbolAddress((void**)&cnt,    g_cnt);
    cudaGetSymbolAddress((void**)&rowptr, g_rowptr);
    cudaGetSymbolAddress((void**)&cursor, g_cursor);
    cudaGetSymbolAddress((void**)&colidx, g_colidx);
    cudaGetSymbolAddress((void**)&bsum,   g_bsum);

    const int nb = (N + 255) / 256;
    dim3 gemm_grid((N + 127) / 128, DFEAT / 64);
    const int aa_blocks    = (N * 2 * 32 + 255) / 256;
    const int agg_blocks   = (N * 32 + 255) / 256;
    const int final_blocks = (N * 32 + 255) / 256;
    const int edge_blocks  = (Etot + 255) / 256;
    const int ws1 = (DFEAT * DHID / 2 + 255) / 256;
    const int ws2 = (DFEAT * DFEAT / 2 + 255) / 256;

    // side stream + events (host objects; see R9 note on lifetime under capture)
    cudaStream_t s1;
    cudaStreamCreateWithFlags(&s1, cudaStreamNonBlocking);
    cudaEvent_t evRoot, evCsr, evW2, evWc;
    cudaEventCreateWithFlags(&evRoot, cudaEventDisableTiming);
    cudaEventCreateWithFlags(&evCsr,  cudaEventDisableTiming);
    cudaEventCreateWithFlags(&evW2,   cudaEventDisableTiming);
    cudaEventCreateWithFlags(&evWc,   cudaEventDisableTiming);

    cudaEventRecord(evRoot, 0);
    cudaStreamWaitEvent(s1, evRoot, 0);

    // launch order keeps gemm1 as the 4th kernel (ncu profile slot)
    wsplit_kernel<<<ws1, 256>>>(W1, w1hi, w1lo, DHID, DFEAT);                       // 1 (s0)
    count_kernel<<<edge_blocks, 256, 0, s1>>>(ei, cnt, E, Etot);                    // 2 (s1)
    wsplit_kernel<<<ws2, 256, 0, s1>>>(W2, w2hi, w2lo, DFEAT, DFEAT);               // 3 (s1)
    gemm_f16_kernel<0><<<gemm_grid, 256>>>(x, w1hi, w1lo, nullptr, h1, N, DFEAT, DHID); // 4 (s0)
    cudaEventRecord(evW2, s1);
    scan_block_sums<<<nb, 256, 0, s1>>>(cnt, bsum, N);                              // 5 (s1)
    scan_bsums<<<1, 256, 0, s1>>>(bsum, nb);                                        // 6 (s1)
    scan_final<<<nb, 256, 0, s1>>>(cnt, bsum, rowptr, cursor, N);                   // 7 (s1)
    scatter_kernel<<<edge_blocks, 256, 0, s1>>>(ei, cursor, colidx, E, Etot);       // 8 (s1)
    cudaEventRecord(evCsr, s1);
    wc_kernel<<<1, 256, 0, s1>>>(Wp1, bp1, Wp2, bp2, wc);                           // 9 (s1)
    cudaEventRecord(evWc, s1);

    // main chain on s0
    alpha_kernel<<<aa_blocks, 256>>>(h1, a_src1, a_dst1, as, ad, N);                // 10
    cudaStreamWaitEvent(0, evCsr, 0);
    agg_csr_kernel<<<agg_blocks, 256>>>(rowptr, cursor, colidx, h1, as, ad, agg1, N); // 11
    cudaStreamWaitEvent(0, evW2, 0);
    gemm_f16_kernel<1><<<gemm_grid, 256>>>(agg1, w2hi, w2lo, b1, h2, N, DFEAT, DFEAT); // 12
    alpha_kernel<<<aa_blocks, 256>>>(h2, a_src2, a_dst2, as, ad, N);                // 13
    agg_csr_kernel<<<agg_blocks, 256>>>(rowptr, cursor, colidx, h2, as, ad, agg2, N); // 14
    cudaStreamWaitEvent(0, evWc, 0);
    final_kernel<<<final_blocks, 256>>>(agg2, b2, wc, (float*)d_out, N);            // 15
}

// round 14
// speedup vs baseline: 1.0662x; 1.0662x over previous
#include <cuda_runtime.h>
#include <cuda_fp16.h>
#include <math.h>
#include <stdint.h>

#define NNODES 50000
#define EEDGES 800000
#define ETOT   (EEDGES + NNODES)
#define DHID   128
#define DFEAT  256          // HEADS * HID
#define NEG_SLOPE 0.2f
#define EPSV 1e-16f

// ---------------- scratch (no allocation allowed; zero-initialized at load) ----------------
__device__ __half g_h1[NNODES * DFEAT];
__device__ float  g_agg1[NNODES * DFEAT];
__device__ __half g_h2[NNODES * DFEAT];
__device__ float  g_agg2[NNODES * DFEAT];
__device__ float  g_as[NNODES * 2];
__device__ float  g_ad[NNODES * 2];
__device__ float  g_wc[DFEAT + 1];
__device__ uint32_t g_w1hi[DFEAT * DHID / 2];   // W1 split, packed k-pairs [N][K/2]
__device__ uint32_t g_w1lo[DFEAT * DHID / 2];
__device__ uint32_t g_w2hi[DFEAT * DFEAT / 2];  // W2 split
__device__ uint32_t g_w2lo[DFEAT * DFEAT / 2];
__device__ int    g_cnt[NNODES];      // self-cleaning (scan_final re-zeroes)
__device__ int    g_rowptr[NNODES];
__device__ int    g_cursor[NNODES];   // after scatter: row end
__device__ int    g_colidx[ETOT];
__device__ int    g_bsum[256];

// ================= weight pre-split: W[k][n] fp32 -> hi/lo fp16 k-pairs [n][k/2] =================
__global__ void wsplit_kernel(const float* __restrict__ W,
                              uint32_t* __restrict__ hi, uint32_t* __restrict__ lo,
                              int K, int N) {
    int t = blockIdx.x * 256 + threadIdx.x;
    int total = N * (K >> 1);
    if (t >= total) return;
    int n = t / (K >> 1), k2 = t % (K >> 1);
    float x = W[(size_t)(2 * k2) * N + n];
    float y = W[(size_t)(2 * k2 + 1) * N + n];
    __half2 h = __floats2half2_rn(x, y);
    float2 hf = __half22float2(h);
    __half2 l = __floats2half2_rn(x - hf.x, y - hf.y);
    hi[t] = *(uint32_t*)&h;
    lo[t] = *(uint32_t*)&l;
}

// ================= CSR construction =================
__global__ void count_kernel(const int* __restrict__ ei, int* __restrict__ cnt,
                             int E, int Etot) {
    int t = blockIdx.x * blockDim.x + threadIdx.x;
    if (t >= Etot) return;
    int d = (t < E) ? ei[E + t] : (t - E);
    atomicAdd(&cnt[d], 1);
}

__global__ void scan_block_sums(const int* __restrict__ cnt, int* __restrict__ bsum, int N) {
    __shared__ int sh[256];
    int tid = threadIdx.x;
    int i = blockIdx.x * 256 + tid;
    sh[tid] = (i < N) ? cnt[i] : 0;
    __syncthreads();
    for (int s = 128; s > 0; s >>= 1) {
        if (tid < s) sh[tid] += sh[tid + s];
        __syncthreads();
    }
    if (tid == 0) bsum[blockIdx.x] = sh[0];
}

__global__ void scan_bsums(int* bsum, int nb) {
    __shared__ int sh[256];
    int tid = threadIdx.x;
    int v0 = (tid < nb) ? bsum[tid] : 0;
    sh[tid] = v0;
    __syncthreads();
    for (int off = 1; off < 256; off <<= 1) {
        int v = (tid >= off) ? sh[tid - off] : 0;
        __syncthreads();
        sh[tid] += v;
        __syncthreads();
    }
    if (tid < nb) bsum[tid] = sh[tid] - v0;   // exclusive
}

__global__ void scan_final(int* __restrict__ cnt, const int* __restrict__ bsum,
                           int* __restrict__ rowptr, int* __restrict__ cursor, int N) {
    __shared__ int sh[256];
    int tid = threadIdx.x;
    int i = blockIdx.x * 256 + tid;
    int v0 = (i < N) ? cnt[i] : 0;
    sh[tid] = v0;
    __syncthreads();
    for (int off = 1; off < 256; off <<= 1) {
        int v = (tid >= off) ? sh[tid - off] : 0;
        __syncthreads();
        sh[tid] += v;
        __syncthreads();
    }
    if (i < N) {
        int excl = sh[tid] - v0 + bsum[blockIdx.x];
        rowptr[i] = excl;
        cursor[i] = excl;
        cnt[i] = 0;   // self-clean for next graph replay
    }
}

__global__ void scatter_kernel(const int* __restrict__ ei, int* __restrict__ cursor,
                               int* __restrict__ colidx, int E, int Etot) {
    int t = blockIdx.x * blockDim.x + threadIdx.x;
    if (t >= Etot) return;
    int s, d;
    if (t < E) { s = ei[t]; d = ei[E + t]; } else { s = d = t - E; }
    int pos = atomicAdd(&cursor[d], 1);
    colidx[pos] = s;
}

// ================= double-fp16 tensor-core GEMM (ldmatrix fragment loads) =================
__device__ __forceinline__ void mma_f16(float* c, const uint32_t* a, const uint32_t* b) {
    asm volatile(
        "mma.sync.aligned.m16n8k16.row.col.f32.f16.f16.f32 "
        "{%0,%1,%2,%3}, {%4,%5,%6,%7}, {%8,%9}, {%0,%1,%2,%3};"
        : "+f"(c[0]), "+f"(c[1]), "+f"(c[2]), "+f"(c[3])
        : "r"(a[0]), "r"(a[1]), "r"(a[2]), "r"(a[3]), "r"(b[0]), "r"(b[1]));
}

__device__ __forceinline__ void ldsm_x4(uint32_t addr, uint32_t* r) {
    asm volatile("ldmatrix.sync.aligned.m8n8.x4.shared.b16 {%0,%1,%2,%3}, [%4];"
                 : "=r"(r[0]), "=r"(r[1]), "=r"(r[2]), "=r"(r[3]) : "r"(addr));
}

template <int FUSE_RELU>
__global__ void __launch_bounds__(256) gemm_f16_kernel(
    const float* __restrict__ A,
    const uint32_t* __restrict__ Whi, const uint32_t* __restrict__ Wlo,
    const float* __restrict__ bias, __half* __restrict__ C,
    int M, int N, int K)
{
    __shared__ uint32_t Ah[128][12];   // [row][k2], stride 48B: LDSM phase-disjoint banks
    __shared__ uint32_t Al[128][12];
    __shared__ uint32_t Bh[64][12];    // [n][k2]
    __shared__ uint32_t Bl[64][12];

    const int tid  = threadIdx.x;
    const int lane = tid & 31;
    const int warp = tid >> 5;
    const int wm   = warp & 3;     // m warp: wm*32
    const int wn   = warp >> 2;    // n warp: wn*32
    const int gid  = lane >> 2;
    const int tig  = lane & 3;
    const int m0 = blockIdx.x * 128;
    const int n0 = blockIdx.y * 64;
    const int K2 = K >> 1;

    // ---- precomputed ldmatrix lane addresses (loop-invariant, single-buffered) ----
    // A (per fm): matrices = (r0-7,s0),(r8-15,s0),(r0-7,s1),(r8-15,s1)
    const int a_row = ((lane >> 3) & 1) * 8 + (lane & 7);
    const int a_seg = lane >> 4;
    uint32_t aA0 = (uint32_t)__cvta_generic_to_shared(&Ah[wm * 32 + a_row][a_seg * 4]);
    uint32_t aA1 = (uint32_t)__cvta_generic_to_shared(&Ah[wm * 32 + 16 + a_row][a_seg * 4]);
    uint32_t aL0 = (uint32_t)__cvta_generic_to_shared(&Al[wm * 32 + a_row][a_seg * 4]);
    uint32_t aL1 = (uint32_t)__cvta_generic_to_shared(&Al[wm * 32 + 16 + a_row][a_seg * 4]);
    // B (per fn-pair p): matrices = (fn_a,s0),(fn_a,s1),(fn_b,s0),(fn_b,s1)
    const int b_m   = lane >> 3;          // 0..3
    const int b_fn  = b_m >> 1;           // 0/1 within pair
    const int b_seg = b_m & 1;
    const int b_row = lane & 7;
    uint32_t aB0 = (uint32_t)__cvta_generic_to_shared(&Bh[wn * 32 + (0 + b_fn) * 8 + b_row][b_seg * 4]);
    uint32_t aB1 = (uint32_t)__cvta_generic_to_shared(&Bh[wn * 32 + (2 + b_fn) * 8 + b_row][b_seg * 4]);
    uint32_t aBl0 = (uint32_t)__cvta_generic_to_shared(&Bl[wn * 32 + (0 + b_fn) * 8 + b_row][b_seg * 4]);
    uint32_t aBl1 = (uint32_t)__cvta_generic_to_shared(&Bl[wn * 32 + (2 + b_fn) * 8 + b_row][b_seg * 4]);

    float c_[2][4][4];
#pragma unroll
    for (int fm = 0; fm < 2; fm++)
#pragma unroll
        for (int fn = 0; fn < 4; fn++)
#pragma unroll
            for (int j = 0; j < 4; j++) c_[fm][fn][j] = 0.f;

    for (int k0 = 0; k0 < K; k0 += 16) {
        // ---- A tile (128 x 16): 512 float4, 2 per thread; split to hi/lo k-pairs ----
#pragma unroll
        for (int it = 0; it < 2; it++) {
            int idx = tid + it * 256;
            int row = idx >> 2, c4 = idx & 3;
            int gm = m0 + row;
            float4 f = make_float4(0.f, 0.f, 0.f, 0.f);
            if (gm < M) f = *(const float4*)&A[(size_t)gm * K + k0 + c4 * 4];
            if (FUSE_RELU) {
                float4 bb = *(const float4*)&bias[k0 + c4 * 4];
                f.x = fmaxf(f.x + bb.x, 0.f);
                f.y = fmaxf(f.y + bb.y, 0.f);
                f.z = fmaxf(f.z + bb.z, 0.f);
                f.w = fmaxf(f.w + bb.w, 0.f);
            }
            __half2 h01 = __floats2half2_rn(f.x, f.y);
            __half2 h23 = __floats2half2_rn(f.z, f.w);
            float2 hf01 = __half22float2(h01);
            float2 hf23 = __half22float2(h23);
            __half2 l01 = __floats2half2_rn(f.x - hf01.x, f.y - hf01.y);
            __half2 l23 = __floats2half2_rn(f.z - hf23.x, f.w - hf23.y);
            *(uint2*)&Ah[row][c4 * 2] = make_uint2(*(uint32_t*)&h01, *(uint32_t*)&h23);
            *(uint2*)&Al[row][c4 * 2] = make_uint2(*(uint32_t*)&l01, *(uint32_t*)&l23);
        }
        // ---- B tile (64 n x 8 k2): 256 uint2, 1 per thread (pre-split weights) ----
        {
            int n = tid >> 2;             // 0..63
            int kq = (tid & 3) * 2;       // 0,2,4,6
            size_t gidx = (size_t)(n0 + n) * K2 + (k0 >> 1) + kq;
            uint2 hv = *(const uint2*)&Whi[gidx];
            uint2 lv = *(const uint2*)&Wlo[gidx];
            *(uint2*)&Bh[n][kq] = hv;
            *(uint2*)&Bl[n][kq] = lv;
        }
        __syncthreads();

        // ---- fragment loads: 8 ldmatrix.x4 replace 32 scalar LDS ----
        uint32_t ah[2][4], al[2][4], bh[4][2], bl[4][2];
        ldsm_x4(aA0, ah[0]);
        ldsm_x4(aA1, ah[1]);
        ldsm_x4(aL0, al[0]);
        ldsm_x4(aL1, al[1]);
        uint32_t bt[4];
        ldsm_x4(aB0, bt);   bh[0][0] = bt[0]; bh[0][1] = bt[1]; bh[1][0] = bt[2]; bh[1][1] = bt[3];
        ldsm_x4(aB1, bt);   bh[2][0] = bt[0]; bh[2][1] = bt[1]; bh[3][0] = bt[2]; bh[3][1] = bt[3];
        ldsm_x4(aBl0, bt);  bl[0][0] = bt[0]; bl[0][1] = bt[1]; bl[1][0] = bt[2]; bl[1][1] = bt[3];
        ldsm_x4(aBl1, bt);  bl[2][0] = bt[0]; bl[2][1] = bt[1]; bl[3][0] = bt[2]; bl[3][1] = bt[3];

#pragma unroll
        for (int fm = 0; fm < 2; fm++)
#pragma unroll
            for (int fn = 0; fn < 4; fn++) {
                mma_f16(c_[fm][fn], ah[fm], bh[fn]);   // hi*hi
                mma_f16(c_[fm][fn], ah[fm], bl[fn]);   // hi*lo
                mma_f16(c_[fm][fn], al[fm], bh[fn]);   // lo*hi
            }
        __syncthreads();
    }

    // ---- epilogue: fp16 stores ----
#pragma unroll
    for (int fm = 0; fm < 2; fm++)
#pragma unroll
        for (int fn = 0; fn < 4; fn++) {
            int gm = m0 + wm * 32 + fm * 16 + gid;
            int gn = n0 + wn * 32 + fn * 8 + 2 * tig;
            if (gm < M)
                *(__half2*)&C[(size_t)gm * N + gn] =
                    __floats2half2_rn(c_[fm][fn][0], c_[fm][fn][1]);
            if (gm + 8 < M)
                *(__half2*)&C[(size_t)(gm + 8) * N + gn] =
                    __floats2half2_rn(c_[fm][fn][2], c_[fm][fn][3]);
        }
}

// ================= attention logits (fp16 h) =================
__global__ void alpha_kernel(const __half* __restrict__ h,
                             const float* __restrict__ a_src,
                             const float* __restrict__ a_dst,
                             float* __restrict__ as_out, float* __restrict__ ad_out,
                             int N)
{
    int gw = (blockIdx.x * blockDim.x + threadIdx.x) >> 5;
    int lane = threadIdx.x & 31;
    if (gw >= N * 2) return;
    int n = gw >> 1, hh = gw & 1;
    const __half2* hp = (const __half2*)(h + (size_t)n * DFEAT + hh * DHID);
    __half2 p0 = hp[lane * 2], p1 = hp[lane * 2 + 1];
    float2 f0 = __half22float2(p0), f1 = __half22float2(p1);
    float4 s = *(const float4*)&a_src[hh * DHID + lane * 4];
    float4 d = *(const float4*)&a_dst[hh * DHID + lane * 4];
    float accs = f0.x * s.x + f0.y * s.y + f1.x * s.z + f1.y * s.w;
    float accd = f0.x * d.x + f0.y * d.y + f1.x * d.z + f1.y * d.w;
#pragma unroll
    for (int o = 16; o; o >>= 1) {
        accs += __shfl_xor_sync(0xffffffffu, accs, o);
        accd += __shfl_xor_sync(0xffffffffu, accd, o);
    }
    if (lane == 0) { as_out[gw] = accs; ad_out[gw] = accd; }
}

// ================= fused CSR softmax-aggregation (R10-validated pipelined form) =================
__global__ void agg_csr_kernel(const int* __restrict__ rowptr, const int* __restrict__ rowend,
                               const int* __restrict__ colidx,
                               const __half* __restrict__ h,
                               const float* __restrict__ as_in, const float* __restrict__ ad_in,
                               float* __restrict__ out, int N)
{
    int gw = (blockIdx.x * blockDim.x + threadIdx.x) >> 5;
    int lane = threadIdx.x & 31;
    if (gw >= N) return;
    int start = rowptr[gw];
    int end   = rowend[gw];
    float2 adv = ((const float2*)ad_in)[gw];
    const uint4* h4 = (const uint4*)h;   // 8 fp16 per uint4; node stride = 32

    float acc[8];
#pragma unroll
    for (int j = 0; j < 8; j++) acc[j] = 0.f;
    float den0 = 0.f, den1 = 0.f;
    const bool head0 = lane < 16;

    // prologue: prefetch edge 0 (deg >= 1 always due to self loop)
    int s = __ldg(&colidx[start]);
    float2 av = ((const float2*)as_in)[s];
    uint4 v = h4[(size_t)s * 32 + lane];

    for (int i = start; i < end; i++) {
        float2 av_c = av;
        uint4 v_c = v;
        if (i + 1 < end) {                      // prefetch next edge while computing current
            int s2 = __ldg(&colidx[i + 1]);
            av = ((const float2*)as_in)[s2];
            v = h4[(size_t)s2 * 32 + lane];
        }
        float e0 = av_c.x + adv.x;  e0 = e0 > 0.f ? e0 : NEG_SLOPE * e0;
        float e1 = av_c.y + adv.y;  e1 = e1 > 0.f ? e1 : NEG_SLOPE * e1;
        float w0 = __expf(e0);
        float w1 = __expf(e1);
        den0 += w0;  den1 += w1;
        float w = head0 ? w0 : w1;
        float2 a = __half22float2(*(const __half2*)&v_c.x);
        float2 b = __half22float2(*(const __half2*)&v_c.y);
        float2 c = __half22float2(*(const __half2*)&v_c.z);
        float2 d = __half22float2(*(const __half2*)&v_c.w);
        acc[0] = fmaf(w, a.x, acc[0]); acc[1] = fmaf(w, a.y, acc[1]);
        acc[2] = fmaf(w, b.x, acc[2]); acc[3] = fmaf(w, b.y, acc[3]);
        acc[4] = fmaf(w, c.x, acc[4]); acc[5] = fmaf(w, c.y, acc[5]);
        acc[6] = fmaf(w, d.x, acc[6]); acc[7] = fmaf(w, d.y, acc[7]);
    }
    float r = 1.f / ((head0 ? den0 : den1) + EPSV);
    float* op = out + (size_t)gw * DFEAT + lane * 8;
    *(float4*)op       = make_float4(acc[0] * r, acc[1] * r, acc[2] * r, acc[3] * r);
    *(float4*)(op + 4) = make_float4(acc[4] * r, acc[5] * r, acc[6] * r, acc[7] * r);
}

// ================= collapsed post-MLP =================
__global__ void wc_kernel(const float* __restrict__ Wp1, const float* __restrict__ bp1,
                          const float* __restrict__ Wp2, const float* __restrict__ bp2,
                          float* __restrict__ wc)
{
    int i = threadIdx.x;  // 256 threads
    float acc = 0.f;
    for (int j = 0; j < DHID; j++) acc += Wp1[i * DHID + j] * Wp2[j];
    wc[i] = acc;
    if (i == 0) {
        float b = 0.f;
        for (int j = 0; j < DHID; j++) b += bp1[j] * Wp2[j];
        wc[DFEAT] = b + bp2[0];
    }
}

__global__ void final_kernel(const float* __restrict__ agg2,
                             const float* __restrict__ b2,
                             const float* __restrict__ wc,
                             float* __restrict__ out, int N)
{
    int gw = (blockIdx.x * blockDim.x + threadIdx.x) >> 5;
    int lane = threadIdx.x & 31;
    if (gw >= N) return;
    const float* hp = agg2 + (size_t)gw * DFEAT;
    float acc = 0.f;
#pragma unroll
    for (int r = 0; r < 2; r++) {
        int cidx = r * 128 + lane * 4;
        float4 v  = *(const float4*)&hp[cidx];
        float4 bb = *(const float4*)&b2[cidx];
        float4 ww = *(const float4*)&wc[cidx];
        acc += fmaxf(v.x + bb.x, 0.f) * ww.x;
        acc += fmaxf(v.y + bb.y, 0.f) * ww.y;
        acc += fmaxf(v.z + bb.z, 0.f) * ww.z;
        acc += fmaxf(v.w + bb.w, 0.f) * ww.w;
    }
#pragma unroll
    for (int o = 16; o; o >>= 1) acc += __shfl_xor_sync(0xffffffffu, acc, o);
    if (lane == 0) {
        float z = acc + wc[DFEAT];
        out[gw] = 1.f / (1.f + expf(-z));
    }
}

// ================= launch (fork-join: CSR/wsplit2/wc overlap gemm1 chain) =================
extern "C" void kernel_launch(void* const* d_in, const int* in_sizes, int n_in,
                              void* d_out, int out_size)
{
    const float* x      = (const float*)d_in[0];
    const int*   ei     = (const int*)  d_in[1];
    const float* W1     = (const float*)d_in[2];
    const float* a_src1 = (const float*)d_in[3];
    const float* a_dst1 = (const float*)d_in[4];
    const float* b1     = (const float*)d_in[5];
    const float* W2     = (const float*)d_in[6];
    const float* a_src2 = (const float*)d_in[7];
    const float* a_dst2 = (const float*)d_in[8];
    const float* b2     = (const float*)d_in[9];
    const float* Wp1    = (const float*)d_in[10];
    const float* bp1    = (const float*)d_in[11];
    const float* Wp2    = (const float*)d_in[12];
    const float* bp2    = (const float*)d_in[13];

    const int N = in_sizes[0] / 128;
    const int E = in_sizes[1] / 2;
    const int Etot = E + N;

    __half *h1, *h2;
    float *agg1, *agg2, *as, *ad, *wc;
    uint32_t *w1hi, *w1lo, *w2hi, *w2lo;
    int *cnt, *rowptr, *cursor, *colidx, *bsum;
    cudaGetSymbolAddress((void**)&h1,   g_h1);
    cudaGetSymbolAddress((void**)&agg1, g_agg1);
    cudaGetSymbolAddress((void**)&h2,   g_h2);
    cudaGetSymbolAddress((void**)&agg2, g_agg2);
    cudaGetSymbolAddress((void**)&as,   g_as);
    cudaGetSymbolAddress((void**)&ad,   g_ad);
    cudaGetSymbolAddress((void**)&wc,   g_wc);
    cudaGetSymbolAddress((void**)&w1hi, g_w1hi);
    cudaGetSymbolAddress((void**)&w1lo, g_w1lo);
    cudaGetSymbolAddress((void**)&w2hi, g_w2hi);
    cudaGetSymbolAddress((void**)&w2lo, g_w2lo);
    cudaGetSymbolAddress((void**)&cnt,    g_cnt);
    cudaGetSymbolAddress((void**)&rowptr, g_rowptr);
    cudaGetSymbolAddress((void**)&cursor, g_cursor);
    cudaGetSymbolAddress((void**)&colidx, g_colidx);
    cudaGetSymbolAddress((void**)&bsum,   g_bsum);

    const int nb = (N + 255) / 256;
    dim3 gemm_grid((N + 127) / 128, DFEAT / 64);
    const int aa_blocks    = (N * 2 * 32 + 255) / 256;
    const int agg_blocks   = (N * 32 + 255) / 256;
    const int final_blocks = (N * 32 + 255) / 256;
    const int edge_blocks  = (Etot + 255) / 256;
    const int ws1 = (DFEAT * DHID / 2 + 255) / 256;
    const int ws2 = (DFEAT * DFEAT / 2 + 255) / 256;

    // side stream + events (host objects; see R9 note on lifetime under capture)
    cudaStream_t s1;
    cudaStreamCreateWithFlags(&s1, cudaStreamNonBlocking);
    cudaEvent_t evRoot, evCsr, evW2, evWc;
    cudaEventCreateWithFlags(&evRoot, cudaEventDisableTiming);
    cudaEventCreateWithFlags(&evCsr,  cudaEventDisableTiming);
    cudaEventCreateWithFlags(&evW2,   cudaEventDisableTiming);
    cudaEventCreateWithFlags(&evWc,   cudaEventDisableTiming);

    cudaEventRecord(evRoot, 0);
    cudaStreamWaitEvent(s1, evRoot, 0);

    // launch order keeps gemm1 as the 4th kernel (ncu profile slot)
    wsplit_kernel<<<ws1, 256>>>(W1, w1hi, w1lo, DHID, DFEAT);                       // 1 (s0)
    count_kernel<<<edge_blocks, 256, 0, s1>>>(ei, cnt, E, Etot);                    // 2 (s1)
    wsplit_kernel<<<ws2, 256, 0, s1>>>(W2, w2hi, w2lo, DFEAT, DFEAT);               // 3 (s1)
    gemm_f16_kernel<0><<<gemm_grid, 256>>>(x, w1hi, w1lo, nullptr, h1, N, DFEAT, DHID); // 4 (s0)
    cudaEventRecord(evW2, s1);
    scan_block_sums<<<nb, 256, 0, s1>>>(cnt, bsum, N);                              // 5 (s1)
    scan_bsums<<<1, 256, 0, s1>>>(bsum, nb);                                        // 6 (s1)
    scan_final<<<nb, 256, 0, s1>>>(cnt, bsum, rowptr, cursor, N);                   // 7 (s1)
    scatter_kernel<<<edge_blocks, 256, 0, s1>>>(ei, cursor, colidx, E, Etot);       // 8 (s1)
    cudaEventRecord(evCsr, s1);
    wc_kernel<<<1, 256, 0, s1>>>(Wp1, bp1, Wp2, bp2, wc);                           // 9 (s1)
    cudaEventRecord(evWc, s1);

    // main chain on s0
    alpha_kernel<<<aa_blocks, 256>>>(h1, a_src1, a_dst1, as, ad, N);                // 10
    cudaStreamWaitEvent(0, evCsr, 0);
    agg_csr_kernel<<<agg_blocks, 256>>>(rowptr, cursor, colidx, h1, as, ad, agg1, N); // 11
    cudaStreamWaitEvent(0, evW2, 0);
    gemm_f16_kernel<1><<<gemm_grid, 256>>>(agg1, w2hi, w2lo, b1, h2, N, DFEAT, DFEAT); // 12
    alpha_kernel<<<aa_blocks, 256>>>(h2, a_src2, a_dst2, as, ad, N);                // 13
    agg_csr_kernel<<<agg_blocks, 256>>>(rowptr, cursor, colidx, h2, as, ad, agg2, N); // 14
    cudaStreamWaitEvent(0, evWc, 0);
    final_kernel<<<final_blocks, 256>>>(agg2, b2, wc, (float*)d_out, N);            // 15
}

// round 16
// speedup vs baseline: 1.1654x; 1.0931x over previous
#include <cuda_runtime.h>
#include <cuda_fp16.h>
#include <math.h>
#include <stdint.h>

#define NNODES 50000
#define EEDGES 800000
#define ETOT   (EEDGES + NNODES)
#define DHID   128
#define DFEAT  256          // HEADS * HID
#define NEG_SLOPE 0.2f
#define EPSV 1e-16f

// ---------------- scratch (no allocation allowed; zero-initialized at load) ----------------
__device__ __half g_h1[NNODES * DFEAT];
__device__ float  g_agg1[NNODES * DFEAT];
__device__ __half g_h2[NNODES * DFEAT];
__device__ float  g_agg2[NNODES * DFEAT];
__device__ float  g_as[NNODES * 2];
__device__ float  g_ad[NNODES * 2];
__device__ float  g_wc[DFEAT + 1];
__device__ uint32_t g_w1hi[DFEAT * DHID / 2];   // W1 split, packed k-pairs [N][K/2]
__device__ uint32_t g_w1lo[DFEAT * DHID / 2];
__device__ uint32_t g_w2hi[DFEAT * DFEAT / 2];  // W2 split
__device__ uint32_t g_w2lo[DFEAT * DFEAT / 2];
__device__ int    g_cnt[NNODES];      // self-cleaning (scan_final re-zeroes)
__device__ int    g_rowptr[NNODES];
__device__ int    g_cursor[NNODES];   // after scatter: row end
__device__ int    g_colidx[ETOT];
__device__ int    g_bsum[256];

// ================= weight pre-split: W[k][n] fp32 -> hi/lo fp16 k-pairs [n][k/2] =================
__global__ void wsplit_kernel(const float* __restrict__ W,
                              uint32_t* __restrict__ hi, uint32_t* __restrict__ lo,
                              int K, int N) {
    int t = blockIdx.x * 256 + threadIdx.x;
    int total = N * (K >> 1);
    if (t >= total) return;
    int n = t / (K >> 1), k2 = t % (K >> 1);
    float x = W[(size_t)(2 * k2) * N + n];
    float y = W[(size_t)(2 * k2 + 1) * N + n];
    __half2 h = __floats2half2_rn(x, y);
    float2 hf = __half22float2(h);
    __half2 l = __floats2half2_rn(x - hf.x, y - hf.y);
    hi[t] = *(uint32_t*)&h;
    lo[t] = *(uint32_t*)&l;
}

// ================= CSR construction =================
__global__ void count_kernel(const int* __restrict__ ei, int* __restrict__ cnt,
                             int E, int Etot) {
    int t = blockIdx.x * blockDim.x + threadIdx.x;
    if (t >= Etot) return;
    int d = (t < E) ? ei[E + t] : (t - E);
    atomicAdd(&cnt[d], 1);
}

__global__ void scan_block_sums(const int* __restrict__ cnt, int* __restrict__ bsum, int N) {
    __shared__ int sh[256];
    int tid = threadIdx.x;
    int i = blockIdx.x * 256 + tid;
    sh[tid] = (i < N) ? cnt[i] : 0;
    __syncthreads();
    for (int s = 128; s > 0; s >>= 1) {
        if (tid < s) sh[tid] += sh[tid + s];
        __syncthreads();
    }
    if (tid == 0) bsum[blockIdx.x] = sh[0];
}

__global__ void scan_bsums(int* bsum, int nb) {
    __shared__ int sh[256];
    int tid = threadIdx.x;
    int v0 = (tid < nb) ? bsum[tid] : 0;
    sh[tid] = v0;
    __syncthreads();
    for (int off = 1; off < 256; off <<= 1) {
        int v = (tid >= off) ? sh[tid - off] : 0;
        __syncthreads();
        sh[tid] += v;
        __syncthreads();
    }
    if (tid < nb) bsum[tid] = sh[tid] - v0;   // exclusive
}

__global__ void scan_final(int* __restrict__ cnt, const int* __restrict__ bsum,
                           int* __restrict__ rowptr, int* __restrict__ cursor, int N) {
    __shared__ int sh[256];
    int tid = threadIdx.x;
    int i = blockIdx.x * 256 + tid;
    int v0 = (i < N) ? cnt[i] : 0;
    sh[tid] = v0;
    __syncthreads();
    for (int off = 1; off < 256; off <<= 1) {
        int v = (tid >= off) ? sh[tid - off] : 0;
        __syncthreads();
        sh[tid] += v;
        __syncthreads();
    }
    if (i < N) {
        int excl = sh[tid] - v0 + bsum[blockIdx.x];
        rowptr[i] = excl;
        cursor[i] = excl;
        cnt[i] = 0;   // self-clean for next graph replay
    }
}

__global__ void scatter_kernel(const int* __restrict__ ei, int* __restrict__ cursor,
                               int* __restrict__ colidx, int E, int Etot) {
    int t = blockIdx.x * blockDim.x + threadIdx.x;
    if (t >= Etot) return;
    int s, d;
    if (t < E) { s = ei[t]; d = ei[E + t]; } else { s = d = t - E; }
    int pos = atomicAdd(&cursor[d], 1);
    colidx[pos] = s;
}

// ================= 2-term fp16 tensor-core GEMM =================
// C = op(A)@W; A quantized to fp16 (same error class as fp16 h storage),
// W kept hi/lo split: C = Ah@Bh + Ah@Bl. 16 MMAs + 24 LDS per k-chunk.
__device__ __forceinline__ void mma_f16(float* c, const uint32_t* a, const uint32_t* b) {
    asm volatile(
        "mma.sync.aligned.m16n8k16.row.col.f32.f16.f16.f32 "
        "{%0,%1,%2,%3}, {%4,%5,%6,%7}, {%8,%9}, {%0,%1,%2,%3};"
        : "+f"(c[0]), "+f"(c[1]), "+f"(c[2]), "+f"(c[3])
        : "r"(a[0]), "r"(a[1]), "r"(a[2]), "r"(a[3]), "r"(b[0]), "r"(b[1]));
}

template <int FUSE_RELU>
__global__ void __launch_bounds__(256) gemm_f16_kernel(
    const float* __restrict__ A,
    const uint32_t* __restrict__ Whi, const uint32_t* __restrict__ Wlo,
    const float* __restrict__ bias, __half* __restrict__ C,
    int M, int N, int K)
{
    __shared__ uint32_t Ah[128][12];   // [row][k2], pad 12: frag bank 12*gid+tig bijective
    __shared__ uint32_t Bh[64][12];    // [n][k2]
    __shared__ uint32_t Bl[64][12];

    const int tid  = threadIdx.x;
    const int lane = tid & 31;
    const int warp = tid >> 5;
    const int wm   = warp & 3;     // m warp: wm*32
    const int wn   = warp >> 2;    // n warp: wn*32
    const int gid  = lane >> 2;
    const int tig  = lane & 3;
    const int m0 = blockIdx.x * 128;
    const int n0 = blockIdx.y * 64;
    const int K2 = K >> 1;

    float c_[2][4][4];
#pragma unroll
    for (int fm = 0; fm < 2; fm++)
#pragma unroll
        for (int fn = 0; fn < 4; fn++)
#pragma unroll
            for (int j = 0; j < 4; j++) c_[fm][fn][j] = 0.f;

    for (int k0 = 0; k0 < K; k0 += 16) {
        // ---- A tile (128 x 16): 512 float4, 2 per thread; fp16 quantize ----
#pragma unroll
        for (int it = 0; it < 2; it++) {
            int idx = tid + it * 256;
            int row = idx >> 2, c4 = idx & 3;
            int gm = m0 + row;
            float4 f = make_float4(0.f, 0.f, 0.f, 0.f);
            if (gm < M) f = *(const float4*)&A[(size_t)gm * K + k0 + c4 * 4];
            if (FUSE_RELU) {
                float4 bb = *(const float4*)&bias[k0 + c4 * 4];
                f.x = fmaxf(f.x + bb.x, 0.f);
                f.y = fmaxf(f.y + bb.y, 0.f);
                f.z = fmaxf(f.z + bb.z, 0.f);
                f.w = fmaxf(f.w + bb.w, 0.f);
            }
            __half2 h01 = __floats2half2_rn(f.x, f.y);
            __half2 h23 = __floats2half2_rn(f.z, f.w);
            *(uint2*)&Ah[row][c4 * 2] = make_uint2(*(uint32_t*)&h01, *(uint32_t*)&h23);
        }
        // ---- B tile (64 n x 8 k2): 256 uint2, 1 per thread (pre-split weights) ----
        {
            int n = tid >> 2;             // 0..63
            int kq = (tid & 3) * 2;       // 0,2,4,6
            size_t gidx = (size_t)(n0 + n) * K2 + (k0 >> 1) + kq;
            uint2 hv = *(const uint2*)&Whi[gidx];
            uint2 lv = *(const uint2*)&Wlo[gidx];
            *(uint2*)&Bh[n][kq] = hv;
            *(uint2*)&Bl[n][kq] = lv;
        }
        __syncthreads();

        uint32_t ah[2][4], bh[4][2], bl[4][2];
#pragma unroll
        for (int fm = 0; fm < 2; fm++) {
            int r = wm * 32 + fm * 16;
            ah[fm][0] = Ah[r + gid][tig];
            ah[fm][1] = Ah[r + gid + 8][tig];
            ah[fm][2] = Ah[r + gid][tig + 4];
            ah[fm][3] = Ah[r + gid + 8][tig + 4];
        }
#pragma unroll
        for (int fn = 0; fn < 4; fn++) {
            int cc = wn * 32 + fn * 8 + gid;
            bh[fn][0] = Bh[cc][tig];     bl[fn][0] = Bl[cc][tig];
            bh[fn][1] = Bh[cc][tig + 4]; bl[fn][1] = Bl[cc][tig + 4];
        }
#pragma unroll
        for (int fm = 0; fm < 2; fm++)
#pragma unroll
            for (int fn = 0; fn < 4; fn++) {
                mma_f16(c_[fm][fn], ah[fm], bh[fn]);   // A*Whi
                mma_f16(c_[fm][fn], ah[fm], bl[fn]);   // A*Wlo
            }
        __syncthreads();
    }

    // ---- epilogue: fp16 stores ----
#pragma unroll
    for (int fm = 0; fm < 2; fm++)
#pragma unroll
        for (int fn = 0; fn < 4; fn++) {
            int gm = m0 + wm * 32 + fm * 16 + gid;
            int gn = n0 + wn * 32 + fn * 8 + 2 * tig;
            if (gm < M)
                *(__half2*)&C[(size_t)gm * N + gn] =
                    __floats2half2_rn(c_[fm][fn][0], c_[fm][fn][1]);
            if (gm + 8 < M)
                *(__half2*)&C[(size_t)(gm + 8) * N + gn] =
                    __floats2half2_rn(c_[fm][fn][2], c_[fm][fn][3]);
        }
}

// ================= attention logits (fp16 h) =================
__global__ void alpha_kernel(const __half* __restrict__ h,
                             const float* __restrict__ a_src,
                             const float* __restrict__ a_dst,
                             float* __restrict__ as_out, float* __restrict__ ad_out,
                             int N)
{
    int gw = (blockIdx.x * blockDim.x + threadIdx.x) >> 5;
    int lane = threadIdx.x & 31;
    if (gw >= N * 2) return;
    int n = gw >> 1, hh = gw & 1;
    const __half2* hp = (const __half2*)(h + (size_t)n * DFEAT + hh * DHID);
    __half2 p0 = hp[lane * 2], p1 = hp[lane * 2 + 1];
    float2 f0 = __half22float2(p0), f1 = __half22float2(p1);
    float4 s = *(const float4*)&a_src[hh * DHID + lane * 4];
    float4 d = *(const float4*)&a_dst[hh * DHID + lane * 4];
    float accs = f0.x * s.x + f0.y * s.y + f1.x * s.z + f1.y * s.w;
    float accd = f0.x * d.x + f0.y * d.y + f1.x * d.z + f1.y * d.w;
#pragma unroll
    for (int o = 16; o; o >>= 1) {
        accs += __shfl_xor_sync(0xffffffffu, accs, o);
        accd += __shfl_xor_sync(0xffffffffu, accd, o);
    }
    if (lane == 0) { as_out[gw] = accs; ad_out[gw] = accd; }
}

// ================= fused CSR softmax-aggregation (R10-validated pipelined form) =================
__global__ void agg_csr_kernel(const int* __restrict__ rowptr, const int* __restrict__ rowend,
                               const int* __restrict__ colidx,
                               const __half* __restrict__ h,
                               const float* __restrict__ as_in, const float* __restrict__ ad_in,
                               float* __restrict__ out, int N)
{
    int gw = (blockIdx.x * blockDim.x + threadIdx.x) >> 5;
    int lane = threadIdx.x & 31;
    if (gw >= N) return;
    int start = rowptr[gw];
    int end   = rowend[gw];
    float2 adv = ((const float2*)ad_in)[gw];
    const uint4* h4 = (const uint4*)h;   // 8 fp16 per uint4; node stride = 32

    float acc[8];
#pragma unroll
    for (int j = 0; j < 8; j++) acc[j] = 0.f;
    float den0 = 0.f, den1 = 0.f;
    const bool head0 = lane < 16;

    // prologue: prefetch edge 0 (deg >= 1 always due to self loop)
    int s = __ldg(&colidx[start]);
    float2 av = ((const float2*)as_in)[s];
    uint4 v = h4[(size_t)s * 32 + lane];

    for (int i = start; i < end; i++) {
        float2 av_c = av;
        uint4 v_c = v;
        if (i + 1 < end) {                      // prefetch next edge while computing current
            int s2 = __ldg(&colidx[i + 1]);
            av = ((const float2*)as_in)[s2];
            v = h4[(size_t)s2 * 32 + lane];
        }
        float e0 = av_c.x + adv.x;  e0 = e0 > 0.f ? e0 : NEG_SLOPE * e0;
        float e1 = av_c.y + adv.y;  e1 = e1 > 0.f ? e1 : NEG_SLOPE * e1;
        float w0 = __expf(e0);
        float w1 = __expf(e1);
        den0 += w0;  den1 += w1;
        float w = head0 ? w0 : w1;
        float2 a = __half22float2(*(const __half2*)&v_c.x);
        float2 b = __half22float2(*(const __half2*)&v_c.y);
        float2 c = __half22float2(*(const __half2*)&v_c.z);
        float2 d = __half22float2(*(const __half2*)&v_c.w);
        acc[0] = fmaf(w, a.x, acc[0]); acc[1] = fmaf(w, a.y, acc[1]);
        acc[2] = fmaf(w, b.x, acc[2]); acc[3] = fmaf(w, b.y, acc[3]);
        acc[4] = fmaf(w, c.x, acc[4]); acc[5] = fmaf(w, c.y, acc[5]);
        acc[6] = fmaf(w, d.x, acc[6]); acc[7] = fmaf(w, d.y, acc[7]);
    }
    float r = 1.f / ((head0 ? den0 : den1) + EPSV);
    float* op = out + (size_t)gw * DFEAT + lane * 8;
    *(float4*)op       = make_float4(acc[0] * r, acc[1] * r, acc[2] * r, acc[3] * r);
    *(float4*)(op + 4) = make_float4(acc[4] * r, acc[5] * r, acc[6] * r, acc[7] * r);
}

// ================= collapsed post-MLP =================
__global__ void wc_kernel(const float* __restrict__ Wp1, const float* __restrict__ bp1,
                          const float* __restrict__ Wp2, const float* __restrict__ bp2,
                          float* __restrict__ wc)
{
    int i = threadIdx.x;  // 256 threads
    float acc = 0.f;
    for (int j = 0; j < DHID; j++) acc += Wp1[i * DHID + j] * Wp2[j];
    wc[i] = acc;
    if (i == 0) {
        float b = 0.f;
        for (int j = 0; j < DHID; j++) b += bp1[j] * Wp2[j];
        wc[DFEAT] = b + bp2[0];
    }
}

__global__ void final_kernel(const float* __restrict__ agg2,
                             const float* __restrict__ b2,
                             const float* __restrict__ wc,
                             float* __restrict__ out, int N)
{
    int gw = (blockIdx.x * blockDim.x + threadIdx.x) >> 5;
    int lane = threadIdx.x & 31;
    if (gw >= N) return;
    const float* hp = agg2 + (size_t)gw * DFEAT;
    float acc = 0.f;
#pragma unroll
    for (int r = 0; r < 2; r++) {
        int cidx = r * 128 + lane * 4;
        float4 v  = *(const float4*)&hp[cidx];
        float4 bb = *(const float4*)&b2[cidx];
        float4 ww = *(const float4*)&wc[cidx];
        acc += fmaxf(v.x + bb.x, 0.f) * ww.x;
        acc += fmaxf(v.y + bb.y, 0.f) * ww.y;
        acc += fmaxf(v.z + bb.z, 0.f) * ww.z;
        acc += fmaxf(v.w + bb.w, 0.f) * ww.w;
    }
#pragma unroll
    for (int o = 16; o; o >>= 1) acc += __shfl_xor_sync(0xffffffffu, acc, o);
    if (lane == 0) {
        float z = acc + wc[DFEAT];
        out[gw] = 1.f / (1.f + expf(-z));
    }
}

// ================= launch (fork-join: CSR/wsplit2/wc overlap gemm1 chain) =================
extern "C" void kernel_launch(void* const* d_in, const int* in_sizes, int n_in,
                              void* d_out, int out_size)
{
    const float* x      = (const float*)d_in[0];
    const int*   ei     = (const int*)  d_in[1];
    const float* W1     = (const float*)d_in[2];
    const float* a_src1 = (const float*)d_in[3];
    const float* a_dst1 = (const float*)d_in[4];
    const float* b1     = (const float*)d_in[5];
    const float* W2     = (const float*)d_in[6];
    const float* a_src2 = (const float*)d_in[7];
    const float* a_dst2 = (const float*)d_in[8];
    const float* b2     = (const float*)d_in[9];
    const float* Wp1    = (const float*)d_in[10];
    const float* bp1    = (const float*)d_in[11];
    const float* Wp2    = (const float*)d_in[12];
    const float* bp2    = (const float*)d_in[13];

    const int N = in_sizes[0] / 128;
    const int E = in_sizes[1] / 2;
    const int Etot = E + N;

    __half *h1, *h2;
    float *agg1, *agg2, *as, *ad, *wc;
    uint32_t *w1hi, *w1lo, *w2hi, *w2lo;
    int *cnt, *rowptr, *cursor, *colidx, *bsum;
    cudaGetSymbolAddress((void**)&h1,   g_h1);
    cudaGetSymbolAddress((void**)&agg1, g_agg1);
    cudaGetSymbolAddress((void**)&h2,   g_h2);
    cudaGetSymbolAddress((void**)&agg2, g_agg2);
    cudaGetSymbolAddress((void**)&as,   g_as);
    cudaGetSymbolAddress((void**)&ad,   g_ad);
    cudaGetSymbolAddress((void**)&wc,   g_wc);
    cudaGetSymbolAddress((void**)&w1hi, g_w1hi);
    cudaGetSymbolAddress((void**)&w1lo, g_w1lo);
    cudaGetSymbolAddress((void**)&w2hi, g_w2hi);
    cudaGetSymbolAddress((void**)&w2lo, g_w2lo);
    cudaGetSymbolAddress((void**)&cnt,    g_cnt);
    cudaGetSymbolAddress((void**)&rowptr, g_rowptr);
    cudaGetSymbolAddress((void**)&cursor, g_cursor);
    cudaGetSymbolAddress((void**)&colidx, g_colidx);
    cudaGetSymbolAddress((void**)&bsum,   g_bsum);

    const int nb = (N + 255) / 256;
    dim3 gemm_grid((N + 127) / 128, DFEAT / 64);
    const int aa_blocks    = (N * 2 * 32 + 255) / 256;
    const int agg_blocks   = (N * 32 + 255) / 256;
    const int final_blocks = (N * 32 + 255) / 256;
    const int edge_blocks  = (Etot + 255) / 256;
    const int ws1 = (DFEAT * DHID / 2 + 255) / 256;
    const int ws2 = (DFEAT * DFEAT / 2 + 255) / 256;

    // side stream + events (host objects; see R9 note on lifetime under capture)
    cudaStream_t s1;
    cudaStreamCreateWithFlags(&s1, cudaStreamNonBlocking);
    cudaEvent_t evRoot, evCsr, evW2, evWc;
    cudaEventCreateWithFlags(&evRoot, cudaEventDisableTiming);
    cudaEventCreateWithFlags(&evCsr,  cudaEventDisableTiming);
    cudaEventCreateWithFlags(&evW2,   cudaEventDisableTiming);
    cudaEventCreateWithFlags(&evWc,   cudaEventDisableTiming);

    cudaEventRecord(evRoot, 0);
    cudaStreamWaitEvent(s1, evRoot, 0);

    // launch order keeps gemm1 as the 4th kernel (ncu profile slot)
    wsplit_kernel<<<ws1, 256>>>(W1, w1hi, w1lo, DHID, DFEAT);                       // 1 (s0)
    count_kernel<<<edge_blocks, 256, 0, s1>>>(ei, cnt, E, Etot);                    // 2 (s1)
    wsplit_kernel<<<ws2, 256, 0, s1>>>(W2, w2hi, w2lo, DFEAT, DFEAT);               // 3 (s1)
    gemm_f16_kernel<0><<<gemm_grid, 256>>>(x, w1hi, w1lo, nullptr, h1, N, DFEAT, DHID); // 4 (s0)
    cudaEventRecord(evW2, s1);
    scan_block_sums<<<nb, 256, 0, s1>>>(cnt, bsum, N);                              // 5 (s1)
    scan_bsums<<<1, 256, 0, s1>>>(bsum, nb);                                        // 6 (s1)
    scan_final<<<nb, 256, 0, s1>>>(cnt, bsum, rowptr, cursor, N);                   // 7 (s1)
    scatter_kernel<<<edge_blocks, 256, 0, s1>>>(ei, cursor, colidx, E, Etot);       // 8 (s1)
    cudaEventRecord(evCsr, s1);
    wc_kernel<<<1, 256, 0, s1>>>(Wp1, bp1, Wp2, bp2, wc);                           // 9 (s1)
    cudaEventRecord(evWc, s1);

    // main chain on s0
    alpha_kernel<<<aa_blocks, 256>>>(h1, a_src1, a_dst1, as, ad, N);                // 10
    cudaStreamWaitEvent(0, evCsr, 0);
    agg_csr_kernel<<<agg_blocks, 256>>>(rowptr, cursor, colidx, h1, as, ad, agg1, N); // 11
    cudaStreamWaitEvent(0, evW2, 0);
    gemm_f16_kernel<1><<<gemm_grid, 256>>>(agg1, w2hi, w2lo, b1, h2, N, DFEAT, DFEAT); // 12
    alpha_kernel<<<aa_blocks, 256>>>(h2, a_src2, a_dst2, as, ad, N);                // 13
    agg_csr_kernel<<<agg_blocks, 256>>>(rowptr, cursor, colidx, h2, as, ad, agg2, N); // 14
    cudaStreamWaitEvent(0, evWc, 0);
    final_kernel<<<final_blocks, 256>>>(agg2, b2, wc, (float*)d_out, N);            // 15
}

// round 17
// speedup vs baseline: 1.2198x; 1.0466x over previous
#include <cuda_runtime.h>
#include <cuda_fp16.h>
#include <math.h>
#include <stdint.h>

#define NNODES 50000
#define EEDGES 800000
#define ETOT   (EEDGES + NNODES)
#define DHID   128
#define DFEAT  256          // HEADS * HID
#define NEG_SLOPE 0.2f
#define EPSV 1e-16f

// ---------------- scratch (no allocation allowed; zero-initialized at load) ----------------
__device__ __half g_xh[NNODES * DHID];      // fp16 copy of x
__device__ __half g_h1[NNODES * DFEAT];
__device__ __half g_a1h[NNODES * DFEAT];    // fp16 relu(agg1+b1)  (gemm2 A operand)
__device__ __half g_h2[NNODES * DFEAT];
__device__ float  g_agg2[NNODES * DFEAT];
__device__ float  g_as[NNODES * 2];
__device__ float  g_ad[NNODES * 2];
__device__ float  g_wc[DFEAT + 1];
__device__ uint32_t g_w1hi[DFEAT * DHID / 2];   // W1 split, packed k-pairs [N][K/2]
__device__ uint32_t g_w1lo[DFEAT * DHID / 2];
__device__ uint32_t g_w2hi[DFEAT * DFEAT / 2];  // W2 split
__device__ uint32_t g_w2lo[DFEAT * DFEAT / 2];
__device__ int    g_cnt[NNODES];      // self-cleaning (scan_final re-zeroes)
__device__ int    g_rowptr[NNODES];
__device__ int    g_cursor[NNODES];   // after scatter: row end
__device__ int    g_colidx[ETOT];
__device__ int    g_bsum[256];

// ================= fp32 -> fp16 convert (x) =================
__global__ void f2h_kernel(const float* __restrict__ x, __half* __restrict__ xh, int n8) {
    int i = blockIdx.x * 256 + threadIdx.x;
    if (i >= n8) return;
    float4 a = *(const float4*)&x[i * 8];
    float4 b = *(const float4*)&x[i * 8 + 4];
    __half2 h0 = __floats2half2_rn(a.x, a.y);
    __half2 h1 = __floats2half2_rn(a.z, a.w);
    __half2 h2 = __floats2half2_rn(b.x, b.y);
    __half2 h3 = __floats2half2_rn(b.z, b.w);
    *(uint4*)&xh[i * 8] = make_uint4(*(uint32_t*)&h0, *(uint32_t*)&h1,
                                     *(uint32_t*)&h2, *(uint32_t*)&h3);
}

// ================= weight pre-split: W[k][n] fp32 -> hi/lo fp16 k-pairs [n][k/2] =================
__global__ void wsplit_kernel(const float* __restrict__ W,
                              uint32_t* __restrict__ hi, uint32_t* __restrict__ lo,
                              int K, int N) {
    int t = blockIdx.x * 256 + threadIdx.x;
    int total = N * (K >> 1);
    if (t >= total) return;
    int n = t / (K >> 1), k2 = t % (K >> 1);
    float x = W[(size_t)(2 * k2) * N + n];
    float y = W[(size_t)(2 * k2 + 1) * N + n];
    __half2 h = __floats2half2_rn(x, y);
    float2 hf = __half22float2(h);
    __half2 l = __floats2half2_rn(x - hf.x, y - hf.y);
    hi[t] = *(uint32_t*)&h;
    lo[t] = *(uint32_t*)&l;
}

// ================= CSR construction =================
__global__ void count_kernel(const int* __restrict__ ei, int* __restrict__ cnt,
                             int E, int Etot) {
    int t = blockIdx.x * blockDim.x + threadIdx.x;
    if (t >= Etot) return;
    int d = (t < E) ? ei[E + t] : (t - E);
    atomicAdd(&cnt[d], 1);
}

__global__ void scan_block_sums(const int* __restrict__ cnt, int* __restrict__ bsum, int N) {
    __shared__ int sh[256];
    int tid = threadIdx.x;
    int i = blockIdx.x * 256 + tid;
    sh[tid] = (i < N) ? cnt[i] : 0;
    __syncthreads();
    for (int s = 128; s > 0; s >>= 1) {
        if (tid < s) sh[tid] += sh[tid + s];
        __syncthreads();
    }
    if (tid == 0) bsum[blockIdx.x] = sh[0];
}

__global__ void scan_bsums(int* bsum, int nb) {
    __shared__ int sh[256];
    int tid = threadIdx.x;
    int v0 = (tid < nb) ? bsum[tid] : 0;
    sh[tid] = v0;
    __syncthreads();
    for (int off = 1; off < 256; off <<= 1) {
        int v = (tid >= off) ? sh[tid - off] : 0;
        __syncthreads();
        sh[tid] += v;
        __syncthreads();
    }
    if (tid < nb) bsum[tid] = sh[tid] - v0;   // exclusive
}

__global__ void scan_final(int* __restrict__ cnt, const int* __restrict__ bsum,
                           int* __restrict__ rowptr, int* __restrict__ cursor, int N) {
    __shared__ int sh[256];
    int tid = threadIdx.x;
    int i = blockIdx.x * 256 + tid;
    int v0 = (i < N) ? cnt[i] : 0;
    sh[tid] = v0;
    __syncthreads();
    for (int off = 1; off < 256; off <<= 1) {
        int v = (tid >= off) ? sh[tid - off] : 0;
        __syncthreads();
        sh[tid] += v;
        __syncthreads();
    }
    if (i < N) {
        int excl = sh[tid] - v0 + bsum[blockIdx.x];
        rowptr[i] = excl;
        cursor[i] = excl;
        cnt[i] = 0;   // self-clean for next graph replay
    }
}

__global__ void scatter_kernel(const int* __restrict__ ei, int* __restrict__ cursor,
                               int* __restrict__ colidx, int E, int Etot) {
    int t = blockIdx.x * blockDim.x + threadIdx.x;
    if (t >= Etot) return;
    int s, d;
    if (t < E) { s = ei[t]; d = ei[E + t]; } else { s = d = t - E; }
    int pos = atomicAdd(&cursor[d], 1);
    colidx[pos] = s;
}

// ================= cp.async helpers =================
__device__ __forceinline__ void cp16(uint32_t dst, const void* src, bool pred) {
    int sz = pred ? 16 : 0;
    asm volatile("cp.async.cg.shared.global [%0], [%1], 16, %2;"
                 :: "r"(dst), "l"(src), "r"(sz));
}
__device__ __forceinline__ void cp_commit() {
    asm volatile("cp.async.commit_group;" ::: "memory");
}
template <int NW>
__device__ __forceinline__ void cp_wait() {
    asm volatile("cp.async.wait_group %0;" :: "n"(NW) : "memory");
}

// ================= 2-term fp16 tensor-core GEMM, cp.async double-buffered =================
// C = A@W; A fp16 in gmem (pre-quantized, bias/relu pre-applied);
// W hi/lo split: C = A@Bh + A@Bl.
__device__ __forceinline__ void mma_f16(float* c, const uint32_t* a, const uint32_t* b) {
    asm volatile(
        "mma.sync.aligned.m16n8k16.row.col.f32.f16.f16.f32 "
        "{%0,%1,%2,%3}, {%4,%5,%6,%7}, {%8,%9}, {%0,%1,%2,%3};"
        : "+f"(c[0]), "+f"(c[1]), "+f"(c[2]), "+f"(c[3])
        : "r"(a[0]), "r"(a[1]), "r"(a[2]), "r"(a[3]), "r"(b[0]), "r"(b[1]));
}

__global__ void __launch_bounds__(256) gemm_f16_kernel(
    const __half* __restrict__ A,
    const uint32_t* __restrict__ Whi, const uint32_t* __restrict__ Wlo,
    __half* __restrict__ C, int M, int N, int K)
{
    __shared__ uint32_t Ah[2][128][12];   // [stage][row][k2], pad 12 (frag banks bijective)
    __shared__ uint32_t Bh[2][64][12];
    __shared__ uint32_t Bl[2][64][12];

    const int tid  = threadIdx.x;
    const int lane = tid & 31;
    const int warp = tid >> 5;
    const int wm   = warp & 3;     // m warp: wm*32
    const int wn   = warp >> 2;    // n warp: wn*32
    const int gid  = lane >> 2;
    const int tig  = lane & 3;
    const int m0 = blockIdx.x * 128;
    const int n0 = blockIdx.y * 64;
    const int K2 = K >> 1;
    const int NK = K >> 4;

    // cp.async lane roles (fixed): A: row=tid>>1, seg=tid&1 (16B = 8 halves)
    //                              B: tid<128 -> Bh, else Bl; s=tid&127: n=s>>1, seg=s&1
    const int a_row = tid >> 1, a_seg = tid & 1;
    const int b_s = tid & 127, b_n = b_s >> 1, b_seg = b_s & 1;
    const bool is_bh = tid < 128;
    const int gm_ld = m0 + a_row;

    auto issue = [&](int st, int k0) {
        uint32_t da = (uint32_t)__cvta_generic_to_shared(&Ah[st][a_row][a_seg * 4]);
        cp16(da, A + (size_t)gm_ld * K + k0 + a_seg * 8, gm_ld < M);
        const uint32_t* bsrc = (is_bh ? Whi : Wlo) + (size_t)(n0 + b_n) * K2 + (k0 >> 1) + b_seg * 4;
        uint32_t db = (uint32_t)__cvta_generic_to_shared(
            is_bh ? &Bh[st][b_n][b_seg * 4] : &Bl[st][b_n][b_seg * 4]);
        cp16(db, bsrc, true);
        cp_commit();
    };

    float c_[2][4][4];
#pragma unroll
    for (int fm = 0; fm < 2; fm++)
#pragma unroll
        for (int fn = 0; fn < 4; fn++)
#pragma unroll
            for (int j = 0; j < 4; j++) c_[fm][fn][j] = 0.f;

    issue(0, 0);
    for (int kc = 0; kc < NK; kc++) {
        int p = kc & 1;
        if (kc + 1 < NK) {
            issue(p ^ 1, (kc + 1) * 16);
            cp_wait<1>();          // stage p complete (older group)
        } else {
            cp_wait<0>();
        }
        __syncthreads();

        uint32_t ah[2][4], bh[4][2], bl[4][2];
#pragma unroll
        for (int fm = 0; fm < 2; fm++) {
            int r = wm * 32 + fm * 16;
            ah[fm][0] = Ah[p][r + gid][tig];
            ah[fm][1] = Ah[p][r + gid + 8][tig];
            ah[fm][2] = Ah[p][r + gid][tig + 4];
            ah[fm][3] = Ah[p][r + gid + 8][tig + 4];
        }
#pragma unroll
        for (int fn = 0; fn < 4; fn++) {
            int cc = wn * 32 + fn * 8 + gid;
            bh[fn][0] = Bh[p][cc][tig];     bl[fn][0] = Bl[p][cc][tig];
            bh[fn][1] = Bh[p][cc][tig + 4]; bl[fn][1] = Bl[p][cc][tig + 4];
        }
#pragma unroll
        for (int fm = 0; fm < 2; fm++)
#pragma unroll
            for (int fn = 0; fn < 4; fn++) {
                mma_f16(c_[fm][fn], ah[fm], bh[fn]);   // A*Whi
                mma_f16(c_[fm][fn], ah[fm], bl[fn]);   // A*Wlo
            }
        __syncthreads();   // done reading stage p before it is refilled at kc+2
    }

    // ---- epilogue: fp16 stores ----
#pragma unroll
    for (int fm = 0; fm < 2; fm++)
#pragma unroll
        for (int fn = 0; fn < 4; fn++) {
            int gm = m0 + wm * 32 + fm * 16 + gid;
            int gn = n0 + wn * 32 + fn * 8 + 2 * tig;
            if (gm < M)
                *(__half2*)&C[(size_t)gm * N + gn] =
                    __floats2half2_rn(c_[fm][fn][0], c_[fm][fn][1]);
            if (gm + 8 < M)
                *(__half2*)&C[(size_t)(gm + 8) * N + gn] =
                    __floats2half2_rn(c_[fm][fn][2], c_[fm][fn][3]);
        }
}

// ================= attention logits (fp16 h) =================
__global__ void alpha_kernel(const __half* __restrict__ h,
                             const float* __restrict__ a_src,
                             const float* __restrict__ a_dst,
                             float* __restrict__ as_out, float* __restrict__ ad_out,
                             int N)
{
    int gw = (blockIdx.x * blockDim.x + threadIdx.x) >> 5;
    int lane = threadIdx.x & 31;
    if (gw >= N * 2) return;
    int n = gw >> 1, hh = gw & 1;
    const __half2* hp = (const __half2*)(h + (size_t)n * DFEAT + hh * DHID);
    __half2 p0 = hp[lane * 2], p1 = hp[lane * 2 + 1];
    float2 f0 = __half22float2(p0), f1 = __half22float2(p1);
    float4 s = *(const float4*)&a_src[hh * DHID + lane * 4];
    float4 d = *(const float4*)&a_dst[hh * DHID + lane * 4];
    float accs = f0.x * s.x + f0.y * s.y + f1.x * s.z + f1.y * s.w;
    float accd = f0.x * d.x + f0.y * d.y + f1.x * d.z + f1.y * d.w;
#pragma unroll
    for (int o = 16; o; o >>= 1) {
        accs += __shfl_xor_sync(0xffffffffu, accs, o);
        accd += __shfl_xor_sync(0xffffffffu, accd, o);
    }
    if (lane == 0) { as_out[gw] = accs; ad_out[gw] = accd; }
}

// ================= fused CSR softmax-aggregation =================
// FUSED=1: writes fp16 relu(result + bias) (next GEMM's A operand).
// FUSED=0: writes fp32 result.
template <int FUSED>
__global__ void agg_csr_kernel(const int* __restrict__ rowptr, const int* __restrict__ rowend,
                               const int* __restrict__ colidx,
                               const __half* __restrict__ h,
                               const float* __restrict__ as_in, const float* __restrict__ ad_in,
                               float* __restrict__ outf, __half* __restrict__ outh,
                               const float* __restrict__ bias, int N)
{
    int gw = (blockIdx.x * blockDim.x + threadIdx.x) >> 5;
    int lane = threadIdx.x & 31;
    if (gw >= N) return;
    int start = rowptr[gw];
    int end   = rowend[gw];
    float2 adv = ((const float2*)ad_in)[gw];
    const uint4* h4 = (const uint4*)h;   // 8 fp16 per uint4; node stride = 32

    float acc[8];
#pragma unroll
    for (int j = 0; j < 8; j++) acc[j] = 0.f;
    float den0 = 0.f, den1 = 0.f;
    const bool head0 = lane < 16;

    // prologue: prefetch edge 0 (deg >= 1 always due to self loop)
    int s = __ldg(&colidx[start]);
    float2 av = ((const float2*)as_in)[s];
    uint4 v = h4[(size_t)s * 32 + lane];

    for (int i = start; i < end; i++) {
        float2 av_c = av;
        uint4 v_c = v;
        if (i + 1 < end) {                      // prefetch next edge while computing current
            int s2 = __ldg(&colidx[i + 1]);
            av = ((const float2*)as_in)[s2];
            v = h4[(size_t)s2 * 32 + lane];
        }
        float e0 = av_c.x + adv.x;  e0 = e0 > 0.f ? e0 : NEG_SLOPE * e0;
        float e1 = av_c.y + adv.y;  e1 = e1 > 0.f ? e1 : NEG_SLOPE * e1;
        float w0 = __expf(e0);
        float w1 = __expf(e1);
        den0 += w0;  den1 += w1;
        float w = head0 ? w0 : w1;
        float2 a = __half22float2(*(const __half2*)&v_c.x);
        float2 b = __half22float2(*(const __half2*)&v_c.y);
        float2 c = __half22float2(*(const __half2*)&v_c.z);
        float2 d = __half22float2(*(const __half2*)&v_c.w);
        acc[0] = fmaf(w, a.x, acc[0]); acc[1] = fmaf(w, a.y, acc[1]);
        acc[2] = fmaf(w, b.x, acc[2]); acc[3] = fmaf(w, b.y, acc[3]);
        acc[4] = fmaf(w, c.x, acc[4]); acc[5] = fmaf(w, c.y, acc[5]);
        acc[6] = fmaf(w, d.x, acc[6]); acc[7] = fmaf(w, d.y, acc[7]);
    }
    float r = 1.f / ((head0 ? den0 : den1) + EPSV);
    if (FUSED) {
        float4 b0 = *(const float4*)&bias[lane * 8];
        float4 b1v = *(const float4*)&bias[lane * 8 + 4];
        float o0 = fmaxf(acc[0] * r + b0.x, 0.f), o1 = fmaxf(acc[1] * r + b0.y, 0.f);
        float o2 = fmaxf(acc[2] * r + b0.z, 0.f), o3 = fmaxf(acc[3] * r + b0.w, 0.f);
        float o4 = fmaxf(acc[4] * r + b1v.x, 0.f), o5 = fmaxf(acc[5] * r + b1v.y, 0.f);
        float o6 = fmaxf(acc[6] * r + b1v.z, 0.f), o7 = fmaxf(acc[7] * r + b1v.w, 0.f);
        __half2 q0 = __floats2half2_rn(o0, o1);
        __half2 q1 = __floats2half2_rn(o2, o3);
        __half2 q2 = __floats2half2_rn(o4, o5);
        __half2 q3 = __floats2half2_rn(o6, o7);
        *(uint4*)&outh[(size_t)gw * DFEAT + lane * 8] =
            make_uint4(*(uint32_t*)&q0, *(uint32_t*)&q1, *(uint32_t*)&q2, *(uint32_t*)&q3);
    } else {
        float* op = outf + (size_t)gw * DFEAT + lane * 8;
        *(float4*)op       = make_float4(acc[0] * r, acc[1] * r, acc[2] * r, acc[3] * r);
        *(float4*)(op + 4) = make_float4(acc[4] * r, acc[5] * r, acc[6] * r, acc[7] * r);
    }
}

// ================= collapsed post-MLP =================
__global__ void wc_kernel(const float* __restrict__ Wp1, const float* __restrict__ bp1,
                          const float* __restrict__ Wp2, const float* __restrict__ bp2,
                          float* __restrict__ wc)
{
    int i = threadIdx.x;  // 256 threads
    float acc = 0.f;
    for (int j = 0; j < DHID; j++) acc += Wp1[i * DHID + j] * Wp2[j];
    wc[i] = acc;
    if (i == 0) {
        float b = 0.f;
        for (int j = 0; j < DHID; j++) b += bp1[j] * Wp2[j];
        wc[DFEAT] = b + bp2[0];
    }
}

__global__ void final_kernel(const float* __restrict__ agg2,
                             const float* __restrict__ b2,
                             const float* __restrict__ wc,
                             float* __restrict__ out, int N)
{
    int gw = (blockIdx.x * blockDim.x + threadIdx.x) >> 5;
    int lane = threadIdx.x & 31;
    if (gw >= N) return;
    const float* hp = agg2 + (size_t)gw * DFEAT;
    float acc = 0.f;
#pragma unroll
    for (int r = 0; r < 2; r++) {
        int cidx = r * 128 + lane * 4;
        float4 v  = *(const float4*)&hp[cidx];
        float4 bb = *(const float4*)&b2[cidx];
        float4 ww = *(const float4*)&wc[cidx];
        acc += fmaxf(v.x + bb.x, 0.f) * ww.x;
        acc += fmaxf(v.y + bb.y, 0.f) * ww.y;
        acc += fmaxf(v.z + bb.z, 0.f) * ww.z;
        acc += fmaxf(v.w + bb.w, 0.f) * ww.w;
    }
#pragma unroll
    for (int o = 16; o; o >>= 1) acc += __shfl_xor_sync(0xffffffffu, acc, o);
    if (lane == 0) {
        float z = acc + wc[DFEAT];
        out[gw] = 1.f / (1.f + expf(-z));
    }
}

// ================= launch (fork-join) =================
extern "C" void kernel_launch(void* const* d_in, const int* in_sizes, int n_in,
                              void* d_out, int out_size)
{
    const float* x      = (const float*)d_in[0];
    const int*   ei     = (const int*)  d_in[1];
    const float* W1     = (const float*)d_in[2];
    const float* a_src1 = (const float*)d_in[3];
    const float* a_dst1 = (const float*)d_in[4];
    const float* b1     = (const float*)d_in[5];
    const float* W2     = (const float*)d_in[6];
    const float* a_src2 = (const float*)d_in[7];
    const float* a_dst2 = (const float*)d_in[8];
    const float* b2     = (const float*)d_in[9];
    const float* Wp1    = (const float*)d_in[10];
    const float* bp1    = (const float*)d_in[11];
    const float* Wp2    = (const float*)d_in[12];
    const float* bp2    = (const float*)d_in[13];

    const int N = in_sizes[0] / 128;
    const int E = in_sizes[1] / 2;
    const int Etot = E + N;

    __half *xh, *h1, *a1h, *h2;
    float *agg2, *as, *ad, *wc;
    uint32_t *w1hi, *w1lo, *w2hi, *w2lo;
    int *cnt, *rowptr, *cursor, *colidx, *bsum;
    cudaGetSymbolAddress((void**)&xh,   g_xh);
    cudaGetSymbolAddress((void**)&h1,   g_h1);
    cudaGetSymbolAddress((void**)&a1h,  g_a1h);
    cudaGetSymbolAddress((void**)&h2,   g_h2);
    cudaGetSymbolAddress((void**)&agg2, g_agg2);
    cudaGetSymbolAddress((void**)&as,   g_as);
    cudaGetSymbolAddress((void**)&ad,   g_ad);
    cudaGetSymbolAddress((void**)&wc,   g_wc);
    cudaGetSymbolAddress((void**)&w1hi, g_w1hi);
    cudaGetSymbolAddress((void**)&w1lo, g_w1lo);
    cudaGetSymbolAddress((void**)&w2hi, g_w2hi);
    cudaGetSymbolAddress((void**)&w2lo, g_w2lo);
    cudaGetSymbolAddress((void**)&cnt,    g_cnt);
    cudaGetSymbolAddress((void**)&rowptr, g_rowptr);
    cudaGetSymbolAddress((void**)&cursor, g_cursor);
    cudaGetSymbolAddress((void**)&colidx, g_colidx);
    cudaGetSymbolAddress((void**)&bsum,   g_bsum);

    const int nb = (N + 255) / 256;
    dim3 gemm_grid((N + 127) / 128, DFEAT / 64);
    const int aa_blocks    = (N * 2 * 32 + 255) / 256;
    const int agg_blocks   = (N * 32 + 255) / 256;
    const int final_blocks = (N * 32 + 255) / 256;
    const int edge_blocks  = (Etot + 255) / 256;
    const int ws1 = (DFEAT * DHID / 2 + 255) / 256;
    const int ws2 = (DFEAT * DFEAT / 2 + 255) / 256;
    const int f2h_blocks = (N * DHID / 8 + 255) / 256;

    // side stream + events (host objects; created per call, not destroyed — see R9 note)
    cudaStream_t s1;
    cudaStreamCreateWithFlags(&s1, cudaStreamNonBlocking);
    cudaEvent_t evRoot, evCsr, evW2, evWc;
    cudaEventCreateWithFlags(&evRoot, cudaEventDisableTiming);
    cudaEventCreateWithFlags(&evCsr,  cudaEventDisableTiming);
    cudaEventCreateWithFlags(&evW2,   cudaEventDisableTiming);
    cudaEventCreateWithFlags(&evWc,   cudaEventDisableTiming);

    cudaEventRecord(evRoot, 0);
    cudaStreamWaitEvent(s1, evRoot, 0);

    // launch order keeps gemm1 as the 4th kernel (ncu profile slot)
    wsplit_kernel<<<ws1, 256>>>(W1, w1hi, w1lo, DHID, DFEAT);                       // 1 (s0)
    count_kernel<<<edge_blocks, 256, 0, s1>>>(ei, cnt, E, Etot);                    // 2 (s1)
    f2h_kernel<<<f2h_blocks, 256>>>(x, xh, N * DHID / 8);                           // 3 (s0)
    gemm_f16_kernel<<<gemm_grid, 256>>>(xh, w1hi, w1lo, h1, N, DFEAT, DHID);        // 4 (s0)
    wsplit_kernel<<<ws2, 256, 0, s1>>>(W2, w2hi, w2lo, DFEAT, DFEAT);               // 5 (s1)
    cudaEventRecord(evW2, s1);
    scan_block_sums<<<nb, 256, 0, s1>>>(cnt, bsum, N);                              // 6 (s1)
    scan_bsums<<<1, 256, 0, s1>>>(bsum, nb);                                        // 7 (s1)
    scan_final<<<nb, 256, 0, s1>>>(cnt, bsum, rowptr, cursor, N);                   // 8 (s1)
    scatter_kernel<<<edge_blocks, 256, 0, s1>>>(ei, cursor, colidx, E, Etot);       // 9 (s1)
    cudaEventRecord(evCsr, s1);
    wc_kernel<<<1, 256, 0, s1>>>(Wp1, bp1, Wp2, bp2, wc);                           // 10 (s1)
    cudaEventRecord(evWc, s1);

    // main chain on s0
    alpha_kernel<<<aa_blocks, 256>>>(h1, a_src1, a_dst1, as, ad, N);                // 11
    cudaStreamWaitEvent(0, evCsr, 0);
    agg_csr_kernel<1><<<agg_blocks, 256>>>(rowptr, cursor, colidx, h1, as, ad,
                                           nullptr, a1h, b1, N);                    // 12
    cudaStreamWaitEvent(0, evW2, 0);
    gemm_f16_kernel<<<gemm_grid, 256>>>(a1h, w2hi, w2lo, h2, N, DFEAT, DFEAT);      // 13
    alpha_kernel<<<aa_blocks, 256>>>(h2, a_src2, a_dst2, as, ad, N);                // 14
    agg_csr_kernel<0><<<agg_blocks, 256>>>(rowptr, cursor, colidx, h2, as, ad,
                                           agg2, nullptr, nullptr, N);              // 15
    cudaStreamWaitEvent(0, evWc, 0);
    final_kernel<<<final_blocks, 256>>>(agg2, b2, wc, (float*)d_out, N);            // 16
}